// round 7
// baseline (speedup 1.0000x reference)
#include <cuda_runtime.h>
#include <cuda.h>
#include <cstdint>

// ============================================================================
// MultiLoraLinear on GB300 (ptxas target = plain sm_103, so NO tcgen05).
// TMA + mbarrier pipeline -> SMEM -> mma.sync m16n8k8 tf32 (fallback HMMA).
//   out[b, s, o] = sum_i x[b, s, i] * weight[adapter_ids[b], o, i]
// B=8, S=2048, IN=4096, OUT=64, L=16, all fp32.
//
// R7 vs R6 (56.0us; all configs plateau 55-58us, every pipe at 50-65%):
//   The common factor was 1.5 SMEM-loads per MMA. R7 uses a k4 split where
//   each compute warp owns the FULL 64x64 output for a 16-wide k slice:
//   A and B each read from SMEM exactly ONCE (1.0 LDS/MMA).
//   - LDS/SM/stage 96KB -> 64KB (crossbar floor 768 -> 512 cyc)
//   - per-warp stage: 64 LDS + 32 CVT + 64 MMA, 32 independent acc targets
//   - acc = 128 regs/thread; 2 CTAs x 160 thr => 204-reg cap (launch_bounds)
//   - 4-way cross-k reduction via SMEM at the end (~500 cyc, <1%)
// ============================================================================

#define DEVINL __device__ __forceinline__

namespace mlora {

constexpr int kB = 8, kS = 2048, kIN = 4096, kOUT = 64;
constexpr int TILE_M = 64;            // x rows per CTA
constexpr int TILE_K = 64;            // fp32 K elems per pipeline stage
constexpr int NITER  = kIN / TILE_K;  // 64
constexpr int NSTAGE = 3;

// Each stage: A = [64 rows x 64 k] fp32 as two [64 x 32] sub-tiles
// (128B rows, TMA SW128); B(W) = [64 rows x 64 k] as two [64 x 32].
constexpr int A_SUB   = TILE_M * 32 * 4;        // 8192
constexpr int B_SUB   = kOUT  * 32 * 4;         // 8192
constexpr int A_BYTES = 2 * A_SUB;              // 16384
constexpr int B_BYTES = 2 * B_SUB;              // 16384
constexpr int STAGE_BYTES = A_BYTES + B_BYTES;  // 32768

constexpr int OFF_FULL  = 0;
constexpr int OFF_EMPTY = OFF_FULL + NSTAGE * 8;
constexpr int OFF_DATA  = 1024;                              // SW128 alignment
constexpr int SMEM_TOTAL = OFF_DATA + NSTAGE * STAGE_BYTES;  // 99328 (x2 = 198KB/SM)

DEVINL uint32_t smem_u32(const void* p) {
    uint32_t a;
    asm("{ .reg .u64 t; cvta.to.shared.u64 t, %1; cvt.u32.u64 %0, t; }"
        : "=r"(a) : "l"(p));
    return a;
}

DEVINL uint32_t elect_one() {
    uint32_t pred;
    asm volatile(
        "{\n\t.reg .pred p;\n\telect.sync _|p, 0xFFFFFFFF;\n\t"
        "selp.b32 %0, 1, 0, p;\n\t}"
        : "=r"(pred));
    return pred;
}

#define MBARRIER_INIT(mbar, count) \
    asm volatile("mbarrier.init.shared.b64 [%0], %1;" \
        :: "r"((uint32_t)(mbar)), "r"((uint32_t)(count)) : "memory")

#define MBARRIER_ARRIVE(mbar) \
    asm volatile("mbarrier.arrive.shared.b64 _, [%0];" \
        :: "r"((uint32_t)(mbar)) : "memory")

#define MBARRIER_EXPECT_TX(mbar, bytes) \
    asm volatile("mbarrier.arrive.expect_tx.shared.b64 _, [%0], %1;" \
        :: "r"((uint32_t)(mbar)), "r"((uint32_t)(bytes)) : "memory")

#define MBARRIER_WAIT_PARITY(mbar, parity) do {                                   \
    uint32_t _m = (uint32_t)(mbar);                                               \
    uint32_t _p = (uint32_t)(parity);                                             \
    uint32_t _done;                                                               \
    asm volatile(                                                                 \
        "{\n\t.reg .pred p;\n\t"                                                  \
        "mbarrier.try_wait.parity.acquire.cta.shared::cta.b64 p, [%1], %2;\n\t"   \
        "selp.b32 %0, 1, 0, p;\n\t}"                                              \
        : "=r"(_done) : "r"(_m), "r"(_p) : "memory");                             \
    if (!_done) {                                                                 \
        asm volatile(                                                             \
            "{\n\t.reg .pred P1;\n\t"                                             \
            "WAIT_LOOP_%=:\n\t"                                                   \
            "mbarrier.try_wait.parity.acquire.cta.shared::cta.b64 P1, [%0], %1, 0x989680;\n\t" \
            "@P1 bra.uni WAIT_DONE_%=;\n\t"                                       \
            "bra.uni WAIT_LOOP_%=;\n\t"                                           \
            "WAIT_DONE_%=:\n\t}"                                                  \
            :: "r"(_m), "r"(_p) : "memory");                                      \
    }                                                                             \
} while (0)

// Producer-side wait: post-wait SMEM writes are async-proxy (TMA) only.
#define MBARRIER_WAIT_PARITY_RELAXED(mbar, parity) do {                           \
    uint32_t _m = (uint32_t)(mbar);                                               \
    uint32_t _p = (uint32_t)(parity);                                             \
    uint32_t _done;                                                               \
    asm volatile(                                                                 \
        "{\n\t.reg .pred p;\n\t"                                                  \
        "mbarrier.try_wait.parity.relaxed.cta.shared::cta.b64 p, [%1], %2, 0x989680;\n\t" \
        "selp.b32 %0, 1, 0, p;\n\t}"                                              \
        : "=r"(_done) : "r"(_m), "r"(_p) : "memory");                             \
    if (!_done) {                                                                 \
        asm volatile(                                                             \
            "{\n\t.reg .pred P1;\n\t"                                             \
            "WAIT_LOOP_%=:\n\t"                                                   \
            "mbarrier.try_wait.parity.relaxed.cta.shared::cta.b64 P1, [%0], %1, 0x989680;\n\t" \
            "@P1 bra.uni WAIT_DONE_%=;\n\t"                                       \
            "bra.uni WAIT_LOOP_%=;\n\t"                                           \
            "WAIT_DONE_%=:\n\t}"                                                  \
            :: "r"(_m), "r"(_p) : "memory");                                      \
    }                                                                             \
} while (0)

#define TMA_LOAD_3D(smem_addr, tensor_map, cx, cy, cz, mbar) \
    asm volatile( \
        "cp.async.bulk.tensor.3d.shared::cta.global.tile.mbarrier::complete_tx::bytes " \
        "[%0], [%1, {%2, %3, %4}], [%5];" \
        :: "r"((uint32_t)(smem_addr)), "l"(tensor_map), \
           "r"((int32_t)(cx)), "r"((int32_t)(cy)), "r"((int32_t)(cz)), \
           "r"((uint32_t)(mbar)) \
        : "memory")

// Round-to-nearest tf32 conversion (A operand only: centers its error at 0).
#define CVT_TF32(dst, src) \
    asm("cvt.rna.tf32.f32 %0, %1;" : "=r"(dst) : "f"(src))

// m16n8k8 tf32 MMA, fp32 accumulate (baseline PTX; fallback HMMA on sm_103).
#define MMA_TF32(d, a, b) \
    asm volatile( \
        "mma.sync.aligned.m16n8k8.row.col.f32.tf32.tf32.f32 " \
        "{%0,%1,%2,%3}, {%4,%5,%6,%7}, {%8,%9}, {%0,%1,%2,%3};" \
        : "+f"((d)[0]), "+f"((d)[1]), "+f"((d)[2]), "+f"((d)[3]) \
        : "r"((a)[0]), "r"((a)[1]), "r"((a)[2]), "r"((a)[3]), \
          "r"((b)[0]), "r"((b)[1]))

// ============================================================================
// Kernel: 160 threads. Warps 0-3 compute: warp kq owns the FULL 64x64 output
// over k slice [kq*16, kq*16+16) of each stage (sub-tile t=kq>>1, ks pair
// (kq&1)*2 + {0,1}). Warp 4 = TMA producer.
// grid = B * (S/64) = 256. blockIdx.x = b*32 + tile. 2 CTAs resident per SM.
// ============================================================================
__global__ void __launch_bounds__(160, 2) mlora_kernel(
    const __grid_constant__ CUtensorMap mapX,
    const __grid_constant__ CUtensorMap mapW,
    const int* __restrict__ adapter_ids,
    float* __restrict__ out)
{
    extern __shared__ char smem[];
    const uint32_t sb = smem_u32(smem);
    const int tid  = threadIdx.x;
    const int wid  = tid >> 5;
    const int lid  = tid & 31;
    const int b    = blockIdx.x >> 5;
    const int tile = blockIdx.x & 31;

    if (tid == 0) {
        #pragma unroll
        for (int s = 0; s < NSTAGE; s++) {
            MBARRIER_INIT(sb + OFF_FULL  + s * 8, 1);  // completed by TMA tx bytes
            MBARRIER_INIT(sb + OFF_EMPTY + s * 8, 4);  // 4 consumer warps arrive
        }
    }
    __syncthreads();

    if (wid == 4) {
        // ---------------- TMA producer ----------------
        if (elect_one()) {
            const int aid = adapter_ids[b];
            int st = 0, ph = 1;  // parity 1: fresh empty barriers pass immediately
            for (int it = 0; it < NITER; it++) {
                MBARRIER_WAIT_PARITY_RELAXED(sb + OFF_EMPTY + st * 8, ph);
                const uint32_t full = sb + OFF_FULL + st * 8;
                MBARRIER_EXPECT_TX(full, STAGE_BYTES);
                const uint32_t base = sb + OFF_DATA + st * STAGE_BYTES;
                #pragma unroll
                for (int t = 0; t < 2; t++) {
                    const int cx = it * TILE_K + t * 32;
                    TMA_LOAD_3D(base + t * A_SUB,           &mapX, cx, tile * TILE_M, b,   full);
                    TMA_LOAD_3D(base + A_BYTES + t * B_SUB, &mapW, cx, 0,             aid, full);
                }
                if (++st == NSTAGE) { st = 0; ph ^= 1; }
            }
        }
        return;
    }

    // ---------------- compute warps (wid 0..3) ----------------
    // Warp kq = wid: full 64 rows x 64 cols, k slice kq*16..kq*16+15.
    // Fragment addressing (TMA SW128 on 128B rows => 16B granule g of row r
    // lands at g ^ (r&7); all fragment loads below are bank-conflict-free).
    const int kq   = wid;
    const int ksub = kq >> 1;          // which 32-k TMA sub-tile
    const int ksLo = (kq & 1) * 2;     // first ks (8-k group) within sub-tile
    const uint32_t sw   = (uint32_t)(lid >> 2) << 4;    // swizzle XOR (row&7)*16
    const uint32_t fRow = (uint32_t)(lid >> 2);          // fragment row 0..7
    const uint32_t lk4  = (uint32_t)(lid & 3) * 4;

    float acc[4][8][4];   // [mt 16-row tiles][nt 8-col tiles][frag] = 128 regs
    #pragma unroll
    for (int mt = 0; mt < 4; mt++)
        #pragma unroll
        for (int nt = 0; nt < 8; nt++)
            #pragma unroll
            for (int i = 0; i < 4; i++) acc[mt][nt][i] = 0.0f;

    int st = 0, ph = 0;
    for (int it = 0; it < NITER; it++) {
        MBARRIER_WAIT_PARITY(sb + OFF_FULL + st * 8, ph);
        const char* base  = smem + OFF_DATA + st * STAGE_BYTES;
        const char* aBase = base + ksub * A_SUB;
        const char* bBase = base + A_BYTES + ksub * B_SUB;

        #pragma unroll
        for (int ks2 = 0; ks2 < 2; ks2++) {
            const int ks = ksLo + ks2;
            const uint32_t kb0 = (uint32_t)(ks * 32 + lk4) ^ sw;  // k = ks*8 + lane%4
            const uint32_t kb1 = kb0 ^ 16u;                       // k + 4

            // B fragments: raw f32 bits (HMMA.TF32 truncates in HW).
            uint32_t bf[8][2];
            #pragma unroll
            for (int nt = 0; nt < 8; nt++) {
                const char* rp = bBase + (fRow + nt * 8) * 128;
                bf[nt][0] = *reinterpret_cast<const uint32_t*>(rp + kb0);
                bf[nt][1] = *reinterpret_cast<const uint32_t*>(rp + kb1);
            }

            #pragma unroll
            for (int mt = 0; mt < 4; mt++) {
                const char* ap = aBase + (fRow + mt * 16) * 128;
                uint32_t af[4];
                CVT_TF32(af[0], *reinterpret_cast<const float*>(ap + kb0));
                CVT_TF32(af[1], *reinterpret_cast<const float*>(ap + 1024 + kb0));
                CVT_TF32(af[2], *reinterpret_cast<const float*>(ap + kb1));
                CVT_TF32(af[3], *reinterpret_cast<const float*>(ap + 1024 + kb1));
                #pragma unroll
                for (int nt = 0; nt < 8; nt++)
                    MMA_TF32(acc[mt][nt], af, bf[nt]);
            }
        }

        // HMMA issue implies all this stage's LDS completed -> safe to recycle.
        __syncwarp();
        if (lid == 0) MBARRIER_ARRIVE(sb + OFF_EMPTY + st * 8);
        if (++st == NSTAGE) { st = 0; ph ^= 1; }
    }

    // ---------------- 4-way cross-k reduction + epilogue ----------------
    // All 4 warps dump acc into per-warp SMEM buffers ([j][lane] layout,
    // conflict-free). After bar.sync, warp w sums slice mt=w across the 4
    // buffers and writes it to GMEM. Stage data area is dead by now.
    {
        asm volatile("bar.sync 1, 128;" ::: "memory");   // all loop reads done
        float* myBuf = reinterpret_cast<float*>(smem + OFF_DATA) + kq * 4096;
        #pragma unroll
        for (int mt = 0; mt < 4; mt++)
            #pragma unroll
            for (int nt = 0; nt < 8; nt++)
                #pragma unroll
                for (int i = 0; i < 4; i++)
                    myBuf[((mt * 8 + nt) * 4 + i) * 32 + lid] = acc[mt][nt][i];
        asm volatile("bar.sync 1, 128;" ::: "memory");

        // Warp kq reduces mt = kq.
        const int mt = kq;
        float r[8][4];
        #pragma unroll
        for (int nt = 0; nt < 8; nt++)
            #pragma unroll
            for (int i = 0; i < 4; i++) {
                const float* p = reinterpret_cast<float*>(smem + OFF_DATA)
                               + ((mt * 8 + nt) * 4 + i) * 32 + lid;
                r[nt][i] = p[0] + p[4096] + p[8192] + p[12288];
            }

        // c0,c1 -> (row = lane/4, cols 2*(lane%4)+{0,1}); c2,c3 -> row+8.
        const size_t rowBase = (size_t)b * kS + (size_t)tile * TILE_M
                             + (size_t)(mt * 16) + (size_t)(lid >> 2);
        const int colBase = (lid & 3) * 2;
        #pragma unroll
        for (int nt = 0; nt < 8; nt++) {
            float* p0 = out + rowBase * kOUT + nt * 8 + colBase;
            float* p1 = out + (rowBase + 8) * kOUT + nt * 8 + colBase;
            *reinterpret_cast<float2*>(p0) = make_float2(r[nt][0], r[nt][1]);
            *reinterpret_cast<float2*>(p1) = make_float2(r[nt][2], r[nt][3]);
        }
    }
}

}  // namespace mlora

// ============================================================================
// Host side
// ============================================================================

typedef CUresult (*PFN_encodeTiled)(
    CUtensorMap*, CUtensorMapDataType, cuuint32_t, void*,
    const cuuint64_t*, const cuuint64_t*, const cuuint32_t*, const cuuint32_t*,
    CUtensorMapInterleave, CUtensorMapSwizzle, CUtensorMapL2promotion,
    CUtensorMapFloatOOBfill);

extern "C" void kernel_launch(void* const* d_in, const int* in_sizes, int n_in,
                              void* d_out, int out_size) {
    (void)in_sizes; (void)n_in; (void)out_size;
    const float* x   = (const float*)d_in[0];
    const int*   ids = (const int*)  d_in[1];
    const float* w   = (const float*)d_in[2];
    float*       out = (float*)d_out;

    PFN_encodeTiled enc = nullptr;
    {
        void* p = nullptr;
        cudaDriverEntryPointQueryResult qr;
#if CUDART_VERSION >= 12050
        cudaGetDriverEntryPointByVersion("cuTensorMapEncodeTiled", &p, 12000,
                                         cudaEnableDefault, &qr);
#else
        cudaGetDriverEntryPoint("cuTensorMapEncodeTiled", &p, cudaEnableDefault, &qr);
#endif
        enc = (PFN_encodeTiled)p;
    }

    CUtensorMap mapX, mapW;
    {
        // x: [B, S, IN] fp32 contiguous; dim0 = IN. Box = 32 x 64 (128B rows, SW128).
        cuuint64_t dims[3]    = {(cuuint64_t)mlora::kIN, (cuuint64_t)mlora::kS,
                                 (cuuint64_t)mlora::kB};
        cuuint64_t strides[2] = {(cuuint64_t)mlora::kIN * 4,
                                 (cuuint64_t)mlora::kS * mlora::kIN * 4};
        cuuint32_t box[3]     = {32, (cuuint32_t)mlora::TILE_M, 1};
        cuuint32_t es[3]      = {1, 1, 1};
        enc(&mapX, CU_TENSOR_MAP_DATA_TYPE_FLOAT32, 3, (void*)x,
            dims, strides, box, es,
            CU_TENSOR_MAP_INTERLEAVE_NONE, CU_TENSOR_MAP_SWIZZLE_128B,
            CU_TENSOR_MAP_L2_PROMOTION_L2_128B, CU_TENSOR_MAP_FLOAT_OOB_FILL_NONE);
    }
    {
        // weight: [L, OUT, IN] fp32 contiguous; dim0 = IN. Box = 32 x 64.
        cuuint64_t dims[3]    = {(cuuint64_t)mlora::kIN, (cuuint64_t)mlora::kOUT,
                                 (cuuint64_t)16};
        cuuint64_t strides[2] = {(cuuint64_t)mlora::kIN * 4,
                                 (cuuint64_t)mlora::kOUT * mlora::kIN * 4};
        cuuint32_t box[3]     = {32, (cuuint32_t)mlora::kOUT, 1};
        cuuint32_t es[3]      = {1, 1, 1};
        enc(&mapW, CU_TENSOR_MAP_DATA_TYPE_FLOAT32, 3, (void*)w,
            dims, strides, box, es,
            CU_TENSOR_MAP_INTERLEAVE_NONE, CU_TENSOR_MAP_SWIZZLE_128B,
            CU_TENSOR_MAP_L2_PROMOTION_L2_128B, CU_TENSOR_MAP_FLOAT_OOB_FILL_NONE);
    }

    cudaFuncSetAttribute(mlora::mlora_kernel,
                         cudaFuncAttributeMaxDynamicSharedMemorySize,
                         mlora::SMEM_TOTAL);

    const int grid = mlora::kB * (mlora::kS / mlora::TILE_M);  // 256
    mlora::mlora_kernel<<<grid, 160, mlora::SMEM_TOTAL>>>(mapX, mapW, ids, out);
}

// round 8
// speedup vs baseline: 1.0318x; 1.0318x over previous
#include <cuda_runtime.h>
#include <cuda.h>
#include <cstdint>

// ============================================================================
// MultiLoraLinear on GB300 (ptxas target = plain sm_103, so NO tcgen05).
// TMA + mbarrier pipeline -> SMEM -> mma.sync m16n8k8 tf32 (fallback HMMA).
//   out[b, s, o] = sum_i x[b, s, i] * weight[adapter_ids[b], o, i]
// B=8, S=2048, IN=4096, OUT=64, L=16, all fp32.
//
// R8 vs R7/R6 (55-58us plateau, tensor pinned at ~53% in EVERY layout):
//   Diagnosis: per-warp load-phase / MMA-burst alternation leaves the tensor
//   pipe idle ~47% of the time; ptxas does not hoist the next k-group's LDS
//   above the previous MMA burst (acc "+f" serialization).
//   Fix (on the R6 base = 2 CTAs/SM, warp=(mh,kh)):
//   - Double-buffered fragment registers; explicit order
//     L0,L1,M0,L2,M1,L3,arrive-empty,M2,M3: every MMA burst consumes
//     fragments loaded >=1 group ago; LDS of group k+1 overlaps MMA of k.
//   - empty-barrier arrive moved before the last 2 MMA bursts (MMAs read
//     registers only) -> producer restarts TMA ~300 cyc earlier per stage.
// ============================================================================

#define DEVINL __device__ __forceinline__

namespace mlora {

constexpr int kB = 8, kS = 2048, kIN = 4096, kOUT = 64;
constexpr int TILE_M = 64;            // x rows per CTA
constexpr int TILE_K = 64;            // fp32 K elems per pipeline stage
constexpr int NITER  = kIN / TILE_K;  // 64
constexpr int NSTAGE = 3;

// Each stage: A = [64 rows x 64 k] fp32 as two [64 x 32] sub-tiles
// (128B rows, TMA SW128); B(W) = [64 rows x 64 k] as two [64 x 32].
constexpr int A_SUB   = TILE_M * 32 * 4;        // 8192
constexpr int B_SUB   = kOUT  * 32 * 4;         // 8192
constexpr int A_BYTES = 2 * A_SUB;              // 16384
constexpr int B_BYTES = 2 * B_SUB;              // 16384
constexpr int STAGE_BYTES = A_BYTES + B_BYTES;  // 32768

constexpr int OFF_FULL  = 0;
constexpr int OFF_EMPTY = OFF_FULL + NSTAGE * 8;
constexpr int OFF_DATA  = 1024;                              // SW128 alignment
constexpr int SMEM_TOTAL = OFF_DATA + NSTAGE * STAGE_BYTES;  // 99328 (x2 = 198KB/SM)

DEVINL uint32_t smem_u32(const void* p) {
    uint32_t a;
    asm("{ .reg .u64 t; cvta.to.shared.u64 t, %1; cvt.u32.u64 %0, t; }"
        : "=r"(a) : "l"(p));
    return a;
}

DEVINL uint32_t elect_one() {
    uint32_t pred;
    asm volatile(
        "{\n\t.reg .pred p;\n\telect.sync _|p, 0xFFFFFFFF;\n\t"
        "selp.b32 %0, 1, 0, p;\n\t}"
        : "=r"(pred));
    return pred;
}

#define MBARRIER_INIT(mbar, count) \
    asm volatile("mbarrier.init.shared.b64 [%0], %1;" \
        :: "r"((uint32_t)(mbar)), "r"((uint32_t)(count)) : "memory")

#define MBARRIER_ARRIVE(mbar) \
    asm volatile("mbarrier.arrive.shared.b64 _, [%0];" \
        :: "r"((uint32_t)(mbar)) : "memory")

#define MBARRIER_EXPECT_TX(mbar, bytes) \
    asm volatile("mbarrier.arrive.expect_tx.shared.b64 _, [%0], %1;" \
        :: "r"((uint32_t)(mbar)), "r"((uint32_t)(bytes)) : "memory")

#define MBARRIER_WAIT_PARITY(mbar, parity) do {                                   \
    uint32_t _m = (uint32_t)(mbar);                                               \
    uint32_t _p = (uint32_t)(parity);                                             \
    uint32_t _done;                                                               \
    asm volatile(                                                                 \
        "{\n\t.reg .pred p;\n\t"                                                  \
        "mbarrier.try_wait.parity.acquire.cta.shared::cta.b64 p, [%1], %2;\n\t"   \
        "selp.b32 %0, 1, 0, p;\n\t}"                                              \
        : "=r"(_done) : "r"(_m), "r"(_p) : "memory");                             \
    if (!_done) {                                                                 \
        asm volatile(                                                             \
            "{\n\t.reg .pred P1;\n\t"                                             \
            "WAIT_LOOP_%=:\n\t"                                                   \
            "mbarrier.try_wait.parity.acquire.cta.shared::cta.b64 P1, [%0], %1, 0x989680;\n\t" \
            "@P1 bra.uni WAIT_DONE_%=;\n\t"                                       \
            "bra.uni WAIT_LOOP_%=;\n\t"                                           \
            "WAIT_DONE_%=:\n\t}"                                                  \
            :: "r"(_m), "r"(_p) : "memory");                                      \
    }                                                                             \
} while (0)

// Producer-side wait: post-wait SMEM writes are async-proxy (TMA) only.
#define MBARRIER_WAIT_PARITY_RELAXED(mbar, parity) do {                           \
    uint32_t _m = (uint32_t)(mbar);                                               \
    uint32_t _p = (uint32_t)(parity);                                             \
    uint32_t _done;                                                               \
    asm volatile(                                                                 \
        "{\n\t.reg .pred p;\n\t"                                                  \
        "mbarrier.try_wait.parity.relaxed.cta.shared::cta.b64 p, [%1], %2, 0x989680;\n\t" \
        "selp.b32 %0, 1, 0, p;\n\t}"                                              \
        : "=r"(_done) : "r"(_m), "r"(_p) : "memory");                             \
    if (!_done) {                                                                 \
        asm volatile(                                                             \
            "{\n\t.reg .pred P1;\n\t"                                             \
            "WAIT_LOOP_%=:\n\t"                                                   \
            "mbarrier.try_wait.parity.relaxed.cta.shared::cta.b64 P1, [%0], %1, 0x989680;\n\t" \
            "@P1 bra.uni WAIT_DONE_%=;\n\t"                                       \
            "bra.uni WAIT_LOOP_%=;\n\t"                                           \
            "WAIT_DONE_%=:\n\t}"                                                  \
            :: "r"(_m), "r"(_p) : "memory");                                      \
    }                                                                             \
} while (0)

#define TMA_LOAD_3D(smem_addr, tensor_map, cx, cy, cz, mbar) \
    asm volatile( \
        "cp.async.bulk.tensor.3d.shared::cta.global.tile.mbarrier::complete_tx::bytes " \
        "[%0], [%1, {%2, %3, %4}], [%5];" \
        :: "r"((uint32_t)(smem_addr)), "l"(tensor_map), \
           "r"((int32_t)(cx)), "r"((int32_t)(cy)), "r"((int32_t)(cz)), \
           "r"((uint32_t)(mbar)) \
        : "memory")

// Round-to-nearest tf32 conversion (A operand only: centers its error at 0).
#define CVT_TF32(dst, src) \
    asm("cvt.rna.tf32.f32 %0, %1;" : "=r"(dst) : "f"(src))

// m16n8k8 tf32 MMA, fp32 accumulate (baseline PTX; fallback HMMA on sm_103).
#define MMA_TF32(d, a, b) \
    asm volatile( \
        "mma.sync.aligned.m16n8k8.row.col.f32.tf32.tf32.f32 " \
        "{%0,%1,%2,%3}, {%4,%5,%6,%7}, {%8,%9}, {%0,%1,%2,%3};" \
        : "+f"((d)[0]), "+f"((d)[1]), "+f"((d)[2]), "+f"((d)[3]) \
        : "r"((a)[0]), "r"((a)[1]), "r"((a)[2]), "r"((a)[3]), \
          "r"((b)[0]), "r"((b)[1]))

// Load one k-group (8 wide) of fragments into buffer `buf` (compile-time).
#define LOAD_FRAGS(buf, ks)                                                  \
    do {                                                                     \
        const uint32_t kb0 = ((uint32_t)((ks) * 32) + lk4) ^ sw;             \
        const uint32_t kb1 = kb0 ^ 16u;                                      \
        _Pragma("unroll")                                                    \
        for (int nt = 0; nt < 8; nt++) {                                     \
            const char* rp = bBase + (bRow + nt * 8) * 128;                  \
            bf[buf][nt][0] = *reinterpret_cast<const uint32_t*>(rp + kb0);   \
            bf[buf][nt][1] = *reinterpret_cast<const uint32_t*>(rp + kb1);   \
        }                                                                    \
        _Pragma("unroll")                                                    \
        for (int mt = 0; mt < 2; mt++) {                                     \
            const char* ap = aBase + (aRow + mt * 16) * 128;                 \
            CVT_TF32(af[buf][mt][0], *reinterpret_cast<const float*>(ap + kb0));        \
            CVT_TF32(af[buf][mt][1], *reinterpret_cast<const float*>(ap + 1024 + kb0)); \
            CVT_TF32(af[buf][mt][2], *reinterpret_cast<const float*>(ap + kb1));        \
            CVT_TF32(af[buf][mt][3], *reinterpret_cast<const float*>(ap + 1024 + kb1)); \
        }                                                                    \
    } while (0)

// Issue the 16-MMA burst for buffer `buf` (compile-time).
#define MMA_FRAGS(buf)                                                       \
    do {                                                                     \
        _Pragma("unroll")                                                    \
        for (int mt = 0; mt < 2; mt++)                                       \
            _Pragma("unroll")                                                \
            for (int nt = 0; nt < 8; nt++)                                   \
                MMA_TF32(acc[mt][nt], af[buf][mt], bf[buf][nt]);             \
    } while (0)

// ============================================================================
// Kernel: 160 threads. Warps 0-3 compute: warp w = (mh=w&1, kh=w>>1) owns
// rows [mh*32,+32) x all 64 cols over K-half kh (= TMA sub-tile t=kh).
// Warp 4 = TMA producer. grid = B * (S/64) = 256. blockIdx.x = b*32 + tile.
// ============================================================================
__global__ void __launch_bounds__(160, 2) mlora_kernel(
    const __grid_constant__ CUtensorMap mapX,
    const __grid_constant__ CUtensorMap mapW,
    const int* __restrict__ adapter_ids,
    float* __restrict__ out)
{
    extern __shared__ char smem[];
    const uint32_t sb = smem_u32(smem);
    const int tid  = threadIdx.x;
    const int wid  = tid >> 5;
    const int lid  = tid & 31;
    const int b    = blockIdx.x >> 5;
    const int tile = blockIdx.x & 31;

    if (tid == 0) {
        #pragma unroll
        for (int s = 0; s < NSTAGE; s++) {
            MBARRIER_INIT(sb + OFF_FULL  + s * 8, 1);  // completed by TMA tx bytes
            MBARRIER_INIT(sb + OFF_EMPTY + s * 8, 4);  // 4 consumer warps arrive
        }
    }
    __syncthreads();

    if (wid == 4) {
        // ---------------- TMA producer ----------------
        if (elect_one()) {
            const int aid = adapter_ids[b];
            int st = 0, ph = 1;  // parity 1: fresh empty barriers pass immediately
            for (int it = 0; it < NITER; it++) {
                MBARRIER_WAIT_PARITY_RELAXED(sb + OFF_EMPTY + st * 8, ph);
                const uint32_t full = sb + OFF_FULL + st * 8;
                MBARRIER_EXPECT_TX(full, STAGE_BYTES);
                const uint32_t base = sb + OFF_DATA + st * STAGE_BYTES;
                #pragma unroll
                for (int t = 0; t < 2; t++) {
                    const int cx = it * TILE_K + t * 32;
                    TMA_LOAD_3D(base + t * A_SUB,           &mapX, cx, tile * TILE_M, b,   full);
                    TMA_LOAD_3D(base + A_BYTES + t * B_SUB, &mapW, cx, 0,             aid, full);
                }
                if (++st == NSTAGE) { st = 0; ph ^= 1; }
            }
        }
        return;
    }

    // ---------------- compute warps (wid 0..3) ----------------
    // Warp (mh, kh): rows [mh*32,+32) x cols [0,64), K-half kh.
    // Fragment addressing (TMA SW128 on 128B rows => 16B granule g of row r
    // lands at g ^ (r&7); all fragment loads below are bank-conflict-free).
    const int mh = wid & 1;
    const int kh = wid >> 1;          // 0..1: which 32-k sub-tile of the stage
    const uint32_t sw   = (uint32_t)(lid >> 2) << 4;    // swizzle XOR (row&7)*16
    const uint32_t aRow = (uint32_t)(mh * 32 + (lid >> 2));
    const uint32_t bRow = (uint32_t)(lid >> 2);
    const uint32_t lk4  = (uint32_t)(lid & 3) * 4;

    float acc[2][8][4];   // [mt 16-row tiles][nt 8-col tiles][frag]
    #pragma unroll
    for (int mt = 0; mt < 2; mt++)
        #pragma unroll
        for (int nt = 0; nt < 8; nt++)
            #pragma unroll
            for (int i = 0; i < 4; i++) acc[mt][nt][i] = 0.0f;

    // Double-buffered fragment registers.
    uint32_t af[2][2][4];
    uint32_t bf[2][8][2];

    int st = 0, ph = 0;
    for (int it = 0; it < NITER; it++) {
        MBARRIER_WAIT_PARITY(sb + OFF_FULL + st * 8, ph);
        const char* base  = smem + OFF_DATA + st * STAGE_BYTES;
        const char* aBase = base + kh * A_SUB;            // this warp's k sub-tile
        const char* bBase = base + A_BYTES + kh * B_SUB;

        // Software-pipelined: each MMA burst consumes fragments loaded one
        // group earlier; loads of group k+1 overlap the MMA burst of k.
        LOAD_FRAGS(0, 0);
        LOAD_FRAGS(1, 1);
        MMA_FRAGS(0);          // ks 0
        LOAD_FRAGS(0, 2);
        MMA_FRAGS(1);          // ks 1
        LOAD_FRAGS(1, 3);

        // All SMEM reads of this stage are issued -> recycle the buffer now,
        // before the last two MMA bursts (they read registers only).
        __syncwarp();
        if (lid == 0) MBARRIER_ARRIVE(sb + OFF_EMPTY + st * 8);

        MMA_FRAGS(0);          // ks 2
        MMA_FRAGS(1);          // ks 3

        if (++st == NSTAGE) { st = 0; ph ^= 1; }
    }

    // ---------------- cross-k reduction + epilogue ----------------
    // Warp pair (kh=0, kh=1) with the same mh share a reduction region.
    // All compute warps sync; kh=1 stashes partials in SMEM as [j][lane]
    // (conflict-free), sync again, kh=0 adds and writes GMEM.
    {
        float* red = reinterpret_cast<float*>(smem + OFF_DATA) + mh * 2048;
        asm volatile("bar.sync 1, 128;" ::: "memory");   // all loop reads done
        if (kh == 1) {
            #pragma unroll
            for (int mt = 0; mt < 2; mt++)
                #pragma unroll
                for (int nt = 0; nt < 8; nt++)
                    #pragma unroll
                    for (int i = 0; i < 4; i++)
                        red[((mt * 8 + nt) * 4 + i) * 32 + lid] = acc[mt][nt][i];
        }
        asm volatile("bar.sync 1, 128;" ::: "memory");
        if (kh == 0) {
            #pragma unroll
            for (int mt = 0; mt < 2; mt++)
                #pragma unroll
                for (int nt = 0; nt < 8; nt++)
                    #pragma unroll
                    for (int i = 0; i < 4; i++)
                        acc[mt][nt][i] += red[((mt * 8 + nt) * 4 + i) * 32 + lid];

            // c0,c1 -> (row = lane/4, cols 2*(lane%4)+{0,1}); c2,c3 -> row+8.
            const size_t rowBase = (size_t)b * kS + (size_t)tile * TILE_M
                                 + (size_t)(mh * 32) + (size_t)(lid >> 2);
            const int colBase = (lid & 3) * 2;
            #pragma unroll
            for (int mt = 0; mt < 2; mt++) {
                #pragma unroll
                for (int nt = 0; nt < 8; nt++) {
                    const size_t r0 = rowBase + mt * 16;
                    float* p0 = out + r0 * kOUT + nt * 8 + colBase;
                    float* p1 = out + (r0 + 8) * kOUT + nt * 8 + colBase;
                    *reinterpret_cast<float2*>(p0) =
                        make_float2(acc[mt][nt][0], acc[mt][nt][1]);
                    *reinterpret_cast<float2*>(p1) =
                        make_float2(acc[mt][nt][2], acc[mt][nt][3]);
                }
            }
        }
    }
}

}  // namespace mlora

// ============================================================================
// Host side
// ============================================================================

typedef CUresult (*PFN_encodeTiled)(
    CUtensorMap*, CUtensorMapDataType, cuuint32_t, void*,
    const cuuint64_t*, const cuuint64_t*, const cuuint32_t*, const cuuint32_t*,
    CUtensorMapInterleave, CUtensorMapSwizzle, CUtensorMapL2promotion,
    CUtensorMapFloatOOBfill);

extern "C" void kernel_launch(void* const* d_in, const int* in_sizes, int n_in,
                              void* d_out, int out_size) {
    (void)in_sizes; (void)n_in; (void)out_size;
    const float* x   = (const float*)d_in[0];
    const int*   ids = (const int*)  d_in[1];
    const float* w   = (const float*)d_in[2];
    float*       out = (float*)d_out;

    PFN_encodeTiled enc = nullptr;
    {
        void* p = nullptr;
        cudaDriverEntryPointQueryResult qr;
#if CUDART_VERSION >= 12050
        cudaGetDriverEntryPointByVersion("cuTensorMapEncodeTiled", &p, 12000,
                                         cudaEnableDefault, &qr);
#else
        cudaGetDriverEntryPoint("cuTensorMapEncodeTiled", &p, cudaEnableDefault, &qr);
#endif
        enc = (PFN_encodeTiled)p;
    }

    CUtensorMap mapX, mapW;
    {
        // x: [B, S, IN] fp32 contiguous; dim0 = IN. Box = 32 x 64 (128B rows, SW128).
        cuuint64_t dims[3]    = {(cuuint64_t)mlora::kIN, (cuuint64_t)mlora::kS,
                                 (cuuint64_t)mlora::kB};
        cuuint64_t strides[2] = {(cuuint64_t)mlora::kIN * 4,
                                 (cuuint64_t)mlora::kS * mlora::kIN * 4};
        cuuint32_t box[3]     = {32, (cuuint32_t)mlora::TILE_M, 1};
        cuuint32_t es[3]      = {1, 1, 1};
        enc(&mapX, CU_TENSOR_MAP_DATA_TYPE_FLOAT32, 3, (void*)x,
            dims, strides, box, es,
            CU_TENSOR_MAP_INTERLEAVE_NONE, CU_TENSOR_MAP_SWIZZLE_128B,
            CU_TENSOR_MAP_L2_PROMOTION_L2_128B, CU_TENSOR_MAP_FLOAT_OOB_FILL_NONE);
    }
    {
        // weight: [L, OUT, IN] fp32 contiguous; dim0 = IN. Box = 32 x 64.
        cuuint64_t dims[3]    = {(cuuint64_t)mlora::kIN, (cuuint64_t)mlora::kOUT,
                                 (cuuint64_t)16};
        cuuint64_t strides[2] = {(cuuint64_t)mlora::kIN * 4,
                                 (cuuint64_t)mlora::kOUT * mlora::kIN * 4};
        cuuint32_t box[3]     = {32, (cuuint32_t)mlora::kOUT, 1};
        cuuint32_t es[3]      = {1, 1, 1};
        enc(&mapW, CU_TENSOR_MAP_DATA_TYPE_FLOAT32, 3, (void*)w,
            dims, strides, box, es,
            CU_TENSOR_MAP_INTERLEAVE_NONE, CU_TENSOR_MAP_SWIZZLE_128B,
            CU_TENSOR_MAP_L2_PROMOTION_L2_128B, CU_TENSOR_MAP_FLOAT_OOB_FILL_NONE);
    }

    cudaFuncSetAttribute(mlora::mlora_kernel,
                         cudaFuncAttributeMaxDynamicSharedMemorySize,
                         mlora::SMEM_TOTAL);

    const int grid = mlora::kB * (mlora::kS / mlora::TILE_M);  // 256
    mlora::mlora_kernel<<<grid, 160, mlora::SMEM_TOTAL>>>(mapX, mapW, ids, out);
}

// round 9
// speedup vs baseline: 1.0810x; 1.0476x over previous
#include <cuda_runtime.h>
#include <cuda.h>
#include <cstdint>

// ============================================================================
// MultiLoraLinear on GB300 (ptxas target = plain sm_103, so NO tcgen05).
// TMA + mbarrier pipeline -> SMEM -> mma.sync m16n8k16 f16 (fallback HMMA).
//   out[b, s, o] = sum_i x[b, s, i] * weight[adapter_ids[b], o, i]
// B=8, S=2048, IN=4096, OUT=64, L=16, all fp32.
//
// R9 vs R3..R8 (six schedules, ALL ~55-58us, ~79 TMACs/s invariant):
//   Conclusion: the fallback HMMA.TF32.m16n8k8 instruction RATE is the wall.
//   Fix: fp16 m16n8k16 = 2048 MACs/inst (2x). fp16-rne on both operands gives
//   rel_err ~4e-4 (slightly BETTER than tf32-with-truncated-B's 4.7e-4).
//   Zero-shuffle fragment build: k is a reduction axis, so A and B may use
//   any agreed k-permutation. HW k-slot (2c,2c+1) := logical (c, c+4), which
//   is exactly the value pair today's conflict-free LDS pattern lands in one
//   lane -> one cvt.rn.f16x2.f32 per fragment register.
//   Base otherwise = R6: 2 CTAs/SM, warp=(mh,kh), TILE_M=64, NSTAGE=3.
// ============================================================================

#define DEVINL __device__ __forceinline__

namespace mlora {

constexpr int kB = 8, kS = 2048, kIN = 4096, kOUT = 64;
constexpr int TILE_M = 64;            // x rows per CTA
constexpr int TILE_K = 64;            // fp32 K elems per pipeline stage
constexpr int NITER  = kIN / TILE_K;  // 64
constexpr int NSTAGE = 3;

// Each stage: A = [64 rows x 64 k] fp32 as two [64 x 32] sub-tiles
// (128B rows, TMA SW128); B(W) = [64 rows x 64 k] as two [64 x 32].
constexpr int A_SUB   = TILE_M * 32 * 4;        // 8192
constexpr int B_SUB   = kOUT  * 32 * 4;         // 8192
constexpr int A_BYTES = 2 * A_SUB;              // 16384
constexpr int B_BYTES = 2 * B_SUB;              // 16384
constexpr int STAGE_BYTES = A_BYTES + B_BYTES;  // 32768

constexpr int OFF_FULL  = 0;
constexpr int OFF_EMPTY = OFF_FULL + NSTAGE * 8;
constexpr int OFF_DATA  = 1024;                              // SW128 alignment
constexpr int SMEM_TOTAL = OFF_DATA + NSTAGE * STAGE_BYTES;  // 99328 (x2 = 198KB/SM)

DEVINL uint32_t smem_u32(const void* p) {
    uint32_t a;
    asm("{ .reg .u64 t; cvta.to.shared.u64 t, %1; cvt.u32.u64 %0, t; }"
        : "=r"(a) : "l"(p));
    return a;
}

DEVINL uint32_t elect_one() {
    uint32_t pred;
    asm volatile(
        "{\n\t.reg .pred p;\n\telect.sync _|p, 0xFFFFFFFF;\n\t"
        "selp.b32 %0, 1, 0, p;\n\t}"
        : "=r"(pred));
    return pred;
}

#define MBARRIER_INIT(mbar, count) \
    asm volatile("mbarrier.init.shared.b64 [%0], %1;" \
        :: "r"((uint32_t)(mbar)), "r"((uint32_t)(count)) : "memory")

#define MBARRIER_ARRIVE(mbar) \
    asm volatile("mbarrier.arrive.shared.b64 _, [%0];" \
        :: "r"((uint32_t)(mbar)) : "memory")

#define MBARRIER_EXPECT_TX(mbar, bytes) \
    asm volatile("mbarrier.arrive.expect_tx.shared.b64 _, [%0], %1;" \
        :: "r"((uint32_t)(mbar)), "r"((uint32_t)(bytes)) : "memory")

#define MBARRIER_WAIT_PARITY(mbar, parity) do {                                   \
    uint32_t _m = (uint32_t)(mbar);                                               \
    uint32_t _p = (uint32_t)(parity);                                             \
    uint32_t _done;                                                               \
    asm volatile(                                                                 \
        "{\n\t.reg .pred p;\n\t"                                                  \
        "mbarrier.try_wait.parity.acquire.cta.shared::cta.b64 p, [%1], %2;\n\t"   \
        "selp.b32 %0, 1, 0, p;\n\t}"                                              \
        : "=r"(_done) : "r"(_m), "r"(_p) : "memory");                             \
    if (!_done) {                                                                 \
        asm volatile(                                                             \
            "{\n\t.reg .pred P1;\n\t"                                             \
            "WAIT_LOOP_%=:\n\t"                                                   \
            "mbarrier.try_wait.parity.acquire.cta.shared::cta.b64 P1, [%0], %1, 0x989680;\n\t" \
            "@P1 bra.uni WAIT_DONE_%=;\n\t"                                       \
            "bra.uni WAIT_LOOP_%=;\n\t"                                           \
            "WAIT_DONE_%=:\n\t}"                                                  \
            :: "r"(_m), "r"(_p) : "memory");                                      \
    }                                                                             \
} while (0)

// Producer-side wait: post-wait SMEM writes are async-proxy (TMA) only.
#define MBARRIER_WAIT_PARITY_RELAXED(mbar, parity) do {                           \
    uint32_t _m = (uint32_t)(mbar);                                               \
    uint32_t _p = (uint32_t)(parity);                                             \
    uint32_t _done;                                                               \
    asm volatile(                                                                 \
        "{\n\t.reg .pred p;\n\t"                                                  \
        "mbarrier.try_wait.parity.relaxed.cta.shared::cta.b64 p, [%1], %2, 0x989680;\n\t" \
        "selp.b32 %0, 1, 0, p;\n\t}"                                              \
        : "=r"(_done) : "r"(_m), "r"(_p) : "memory");                             \
    if (!_done) {                                                                 \
        asm volatile(                                                             \
            "{\n\t.reg .pred P1;\n\t"                                             \
            "WAIT_LOOP_%=:\n\t"                                                   \
            "mbarrier.try_wait.parity.relaxed.cta.shared::cta.b64 P1, [%0], %1, 0x989680;\n\t" \
            "@P1 bra.uni WAIT_DONE_%=;\n\t"                                       \
            "bra.uni WAIT_LOOP_%=;\n\t"                                           \
            "WAIT_DONE_%=:\n\t}"                                                  \
            :: "r"(_m), "r"(_p) : "memory");                                      \
    }                                                                             \
} while (0)

#define TMA_LOAD_3D(smem_addr, tensor_map, cx, cy, cz, mbar) \
    asm volatile( \
        "cp.async.bulk.tensor.3d.shared::cta.global.tile.mbarrier::complete_tx::bytes " \
        "[%0], [%1, {%2, %3, %4}], [%5];" \
        :: "r"((uint32_t)(smem_addr)), "l"(tensor_map), \
           "r"((int32_t)(cx)), "r"((int32_t)(cy)), "r"((int32_t)(cz)), \
           "r"((uint32_t)(mbar)) \
        : "memory")

// Pack two f32 into one f16x2 register, round-to-nearest-even.
// Half order is irrelevant for correctness as long as A and B agree
// (k is a reduction axis; both use the same order below).
#define CVT_F16X2(dst, vlo, vhi) \
    asm("cvt.rn.f16x2.f32 %0, %1, %2;" : "=r"(dst) : "f"(vhi), "f"(vlo))

// m16n8k16 f16 MMA, fp32 accumulate (baseline PTX; fallback HMMA on sm_103).
#define MMA_F16(d, a, b) \
    asm volatile( \
        "mma.sync.aligned.m16n8k16.row.col.f32.f16.f16.f32 " \
        "{%0,%1,%2,%3}, {%4,%5,%6,%7}, {%8,%9}, {%0,%1,%2,%3};" \
        : "+f"((d)[0]), "+f"((d)[1]), "+f"((d)[2]), "+f"((d)[3]) \
        : "r"((a)[0]), "r"((a)[1]), "r"((a)[2]), "r"((a)[3]), \
          "r"((b)[0]), "r"((b)[1]))

// ============================================================================
// Kernel: 160 threads. Warps 0-3 compute: warp w = (mh=w&1, kh=w>>1) owns
// rows [mh*32,+32) x all 64 cols over K-half kh (= TMA sub-tile t=kh).
// Warp 4 = TMA producer. grid = B * (S/64) = 256. blockIdx.x = b*32 + tile.
// ============================================================================
__global__ void __launch_bounds__(160, 2) mlora_kernel(
    const __grid_constant__ CUtensorMap mapX,
    const __grid_constant__ CUtensorMap mapW,
    const int* __restrict__ adapter_ids,
    float* __restrict__ out)
{
    extern __shared__ char smem[];
    const uint32_t sb = smem_u32(smem);
    const int tid  = threadIdx.x;
    const int wid  = tid >> 5;
    const int lid  = tid & 31;
    const int b    = blockIdx.x >> 5;
    const int tile = blockIdx.x & 31;

    if (tid == 0) {
        #pragma unroll
        for (int s = 0; s < NSTAGE; s++) {
            MBARRIER_INIT(sb + OFF_FULL  + s * 8, 1);  // completed by TMA tx bytes
            MBARRIER_INIT(sb + OFF_EMPTY + s * 8, 4);  // 4 consumer warps arrive
        }
    }
    __syncthreads();

    if (wid == 4) {
        // ---------------- TMA producer ----------------
        if (elect_one()) {
            const int aid = adapter_ids[b];
            int st = 0, ph = 1;  // parity 1: fresh empty barriers pass immediately
            for (int it = 0; it < NITER; it++) {
                MBARRIER_WAIT_PARITY_RELAXED(sb + OFF_EMPTY + st * 8, ph);
                const uint32_t full = sb + OFF_FULL + st * 8;
                MBARRIER_EXPECT_TX(full, STAGE_BYTES);
                const uint32_t base = sb + OFF_DATA + st * STAGE_BYTES;
                #pragma unroll
                for (int t = 0; t < 2; t++) {
                    const int cx = it * TILE_K + t * 32;
                    TMA_LOAD_3D(base + t * A_SUB,           &mapX, cx, tile * TILE_M, b,   full);
                    TMA_LOAD_3D(base + A_BYTES + t * B_SUB, &mapW, cx, 0,             aid, full);
                }
                if (++st == NSTAGE) { st = 0; ph ^= 1; }
            }
        }
        return;
    }

    // ---------------- compute warps (wid 0..3) ----------------
    // Warp (mh, kh): rows [mh*32,+32) x cols [0,64), K-half kh.
    // Fragment addressing (TMA SW128 on 128B rows => 16B granule g of row r
    // lands at g ^ (r&7); all fragment loads below are bank-conflict-free,
    // identical pattern to the tf32 version).
    // f16 k16 fragments with agreed k-permutation:
    //   HW k-slots (2c, 2c+1)   := logical k (c,   c+4)   [bytes +4c, +4c+16]
    //   HW k-slots (2c+8,2c+9)  := logical k (c+8, c+12)  [bytes +32+4c, +48+4c]
    const int mh = wid & 1;
    const int kh = wid >> 1;          // 0..1: which 32-k sub-tile of the stage
    const uint32_t sw   = (uint32_t)(lid >> 2) << 4;    // swizzle XOR (row&7)*16
    const uint32_t aRow = (uint32_t)(mh * 32 + (lid >> 2));
    const uint32_t bRow = (uint32_t)(lid >> 2);
    const uint32_t lk4  = (uint32_t)(lid & 3) * 4;

    float acc[2][8][4];   // [mt 16-row tiles][nt 8-col tiles][frag]
    #pragma unroll
    for (int mt = 0; mt < 2; mt++)
        #pragma unroll
        for (int nt = 0; nt < 8; nt++)
            #pragma unroll
            for (int i = 0; i < 4; i++) acc[mt][nt][i] = 0.0f;

    int st = 0, ph = 0;
    for (int it = 0; it < NITER; it++) {
        MBARRIER_WAIT_PARITY(sb + OFF_FULL + st * 8, ph);
        const char* base  = smem + OFF_DATA + st * STAGE_BYTES;
        const char* aBase = base + kh * A_SUB;            // this warp's k sub-tile
        const char* bBase = base + A_BYTES + kh * B_SUB;

        #pragma unroll
        for (int grp = 0; grp < 2; grp++) {               // two k16 groups per sub-tile
            // Logical byte offsets for this group's low-8 and high-8 k values.
            // Low bits (0..4) of the pre-XOR logical offset never carry into
            // bit 4 (lk4 <= 12, bases are multiples of 32), so +16 == ^16.
            const uint32_t kbLo = (uint32_t)(grp * 64 + lk4) ^ sw;        // k c / c+4
            const uint32_t kbHi = (uint32_t)(grp * 64 + 32 + lk4) ^ sw;   // k 8+c / 12+c

            // B fragments: 8 n-tiles x 2 f16x2 regs.
            uint32_t bf[8][2];
            #pragma unroll
            for (int nt = 0; nt < 8; nt++) {
                const char* rp = bBase + (bRow + nt * 8) * 128;
                CVT_F16X2(bf[nt][0],
                          *reinterpret_cast<const float*>(rp + kbLo),
                          *reinterpret_cast<const float*>(rp + (kbLo ^ 16u)));
                CVT_F16X2(bf[nt][1],
                          *reinterpret_cast<const float*>(rp + kbHi),
                          *reinterpret_cast<const float*>(rp + (kbHi ^ 16u)));
            }

            #pragma unroll
            for (int mt = 0; mt < 2; mt++) {
                const char* ap = aBase + (aRow + mt * 16) * 128;
                uint32_t af[4];
                CVT_F16X2(af[0],
                          *reinterpret_cast<const float*>(ap + kbLo),
                          *reinterpret_cast<const float*>(ap + (kbLo ^ 16u)));
                CVT_F16X2(af[1],
                          *reinterpret_cast<const float*>(ap + 1024 + kbLo),
                          *reinterpret_cast<const float*>(ap + 1024 + (kbLo ^ 16u)));
                CVT_F16X2(af[2],
                          *reinterpret_cast<const float*>(ap + kbHi),
                          *reinterpret_cast<const float*>(ap + (kbHi ^ 16u)));
                CVT_F16X2(af[3],
                          *reinterpret_cast<const float*>(ap + 1024 + kbHi),
                          *reinterpret_cast<const float*>(ap + 1024 + (kbHi ^ 16u)));
                #pragma unroll
                for (int nt = 0; nt < 8; nt++)
                    MMA_F16(acc[mt][nt], af, bf[nt]);
            }
        }

        // HMMA issue implies all this stage's LDS completed -> safe to recycle.
        __syncwarp();
        if (lid == 0) MBARRIER_ARRIVE(sb + OFF_EMPTY + st * 8);
        if (++st == NSTAGE) { st = 0; ph ^= 1; }
    }

    // ---------------- cross-k reduction + epilogue ----------------
    // Warp pair (kh=0, kh=1) with the same mh share a reduction region.
    // All compute warps sync; kh=1 stashes partials in SMEM as [j][lane]
    // (conflict-free), sync again, kh=0 adds and writes GMEM.
    {
        float* red = reinterpret_cast<float*>(smem + OFF_DATA) + mh * 2048;
        asm volatile("bar.sync 1, 128;" ::: "memory");   // all loop reads done
        if (kh == 1) {
            #pragma unroll
            for (int mt = 0; mt < 2; mt++)
                #pragma unroll
                for (int nt = 0; nt < 8; nt++)
                    #pragma unroll
                    for (int i = 0; i < 4; i++)
                        red[((mt * 8 + nt) * 4 + i) * 32 + lid] = acc[mt][nt][i];
        }
        asm volatile("bar.sync 1, 128;" ::: "memory");
        if (kh == 0) {
            #pragma unroll
            for (int mt = 0; mt < 2; mt++)
                #pragma unroll
                for (int nt = 0; nt < 8; nt++)
                    #pragma unroll
                    for (int i = 0; i < 4; i++)
                        acc[mt][nt][i] += red[((mt * 8 + nt) * 4 + i) * 32 + lid];

            // c0,c1 -> (row = lane/4, cols 2*(lane%4)+{0,1}); c2,c3 -> row+8.
            const size_t rowBase = (size_t)b * kS + (size_t)tile * TILE_M
                                 + (size_t)(mh * 32) + (size_t)(lid >> 2);
            const int colBase = (lid & 3) * 2;
            #pragma unroll
            for (int mt = 0; mt < 2; mt++) {
                #pragma unroll
                for (int nt = 0; nt < 8; nt++) {
                    const size_t r0 = rowBase + mt * 16;
                    float* p0 = out + r0 * kOUT + nt * 8 + colBase;
                    float* p1 = out + (r0 + 8) * kOUT + nt * 8 + colBase;
                    *reinterpret_cast<float2*>(p0) =
                        make_float2(acc[mt][nt][0], acc[mt][nt][1]);
                    *reinterpret_cast<float2*>(p1) =
                        make_float2(acc[mt][nt][2], acc[mt][nt][3]);
                }
            }
        }
    }
}

}  // namespace mlora

// ============================================================================
// Host side
// ============================================================================

typedef CUresult (*PFN_encodeTiled)(
    CUtensorMap*, CUtensorMapDataType, cuuint32_t, void*,
    const cuuint64_t*, const cuuint64_t*, const cuuint32_t*, const cuuint32_t*,
    CUtensorMapInterleave, CUtensorMapSwizzle, CUtensorMapL2promotion,
    CUtensorMapFloatOOBfill);

extern "C" void kernel_launch(void* const* d_in, const int* in_sizes, int n_in,
                              void* d_out, int out_size) {
    (void)in_sizes; (void)n_in; (void)out_size;
    const float* x   = (const float*)d_in[0];
    const int*   ids = (const int*)  d_in[1];
    const float* w   = (const float*)d_in[2];
    float*       out = (float*)d_out;

    PFN_encodeTiled enc = nullptr;
    {
        void* p = nullptr;
        cudaDriverEntryPointQueryResult qr;
#if CUDART_VERSION >= 12050
        cudaGetDriverEntryPointByVersion("cuTensorMapEncodeTiled", &p, 12000,
                                         cudaEnableDefault, &qr);
#else
        cudaGetDriverEntryPoint("cuTensorMapEncodeTiled", &p, cudaEnableDefault, &qr);
#endif
        enc = (PFN_encodeTiled)p;
    }

    CUtensorMap mapX, mapW;
    {
        // x: [B, S, IN] fp32 contiguous; dim0 = IN. Box = 32 x 64 (128B rows, SW128).
        cuuint64_t dims[3]    = {(cuuint64_t)mlora::kIN, (cuuint64_t)mlora::kS,
                                 (cuuint64_t)mlora::kB};
        cuuint64_t strides[2] = {(cuuint64_t)mlora::kIN * 4,
                                 (cuuint64_t)mlora::kS * mlora::kIN * 4};
        cuuint32_t box[3]     = {32, (cuuint32_t)mlora::TILE_M, 1};
        cuuint32_t es[3]      = {1, 1, 1};
        enc(&mapX, CU_TENSOR_MAP_DATA_TYPE_FLOAT32, 3, (void*)x,
            dims, strides, box, es,
            CU_TENSOR_MAP_INTERLEAVE_NONE, CU_TENSOR_MAP_SWIZZLE_128B,
            CU_TENSOR_MAP_L2_PROMOTION_L2_128B, CU_TENSOR_MAP_FLOAT_OOB_FILL_NONE);
    }
    {
        // weight: [L, OUT, IN] fp32 contiguous; dim0 = IN. Box = 32 x 64.
        cuuint64_t dims[3]    = {(cuuint64_t)mlora::kIN, (cuuint64_t)mlora::kOUT,
                                 (cuuint64_t)16};
        cuuint64_t strides[2] = {(cuuint64_t)mlora::kIN * 4,
                                 (cuuint64_t)mlora::kOUT * mlora::kIN * 4};
        cuuint32_t box[3]     = {32, (cuuint32_t)mlora::kOUT, 1};
        cuuint32_t es[3]      = {1, 1, 1};
        enc(&mapW, CU_TENSOR_MAP_DATA_TYPE_FLOAT32, 3, (void*)w,
            dims, strides, box, es,
            CU_TENSOR_MAP_INTERLEAVE_NONE, CU_TENSOR_MAP_SWIZZLE_128B,
            CU_TENSOR_MAP_L2_PROMOTION_L2_128B, CU_TENSOR_MAP_FLOAT_OOB_FILL_NONE);
    }

    cudaFuncSetAttribute(mlora::mlora_kernel,
                         cudaFuncAttributeMaxDynamicSharedMemorySize,
                         mlora::SMEM_TOTAL);

    const int grid = mlora::kB * (mlora::kS / mlora::TILE_M);  // 256
    mlora::mlora_kernel<<<grid, 160, mlora::SMEM_TOTAL>>>(mapX, mapW, ids, out);
}